// round 6
// baseline (speedup 1.0000x reference)
#include <cuda_runtime.h>
#include <cuda_fp16.h>

#define N_NODES 50000
#define N_EDGES 1600000
#define BATCH 4
#define T_STEPS 50
#define DT 0.02f
#define SIM_CTAS 592          // 4 CTAs/SM x 148 SMs (GB300 has >=148); residency enforced below
#define NT 1563               // ceil(N_NODES / 32) tiles of 32 nodes

// ---------------- static device scratch (no allocations allowed) ----------------
__device__ __align__(16) int g_cnt[N_NODES];
__device__ int      g_row[N_NODES + 1];
__device__ int      g_cur[N_NODES];
__device__ unsigned g_edges[N_EDGES];      // lo16 = src node, hi16 = half(weight); target-sorted
__device__ float2   g_ab[N_NODES];         // {alpha, alpha*bias}
__device__ float4   g_vstate[N_NODES];     // fp32 state, node-major x 4 batches (owner-private)
__device__ uint2    g_rates[2][N_NODES];   // half4 relu(v), double-buffered
__device__ unsigned g_arrive;
__device__ volatile unsigned g_epoch;

// ---------------- preprocessing ----------------

__global__ void zero_cnt_kernel() {
    int n = blockIdx.x * blockDim.x + threadIdx.x;
    if (n < N_NODES) g_cnt[n] = 0;
}

__global__ void hist_kernel(const int* __restrict__ tgt) {
    int e = blockIdx.x * blockDim.x + threadIdx.x;
    if (e < N_EDGES) atomicAdd(&g_cnt[tgt[e]], 1);
}

// Single-CTA exclusive scan of g_cnt -> g_row/g_cur. 1024 threads, 4 elems/thread.
__global__ void scan_kernel() {
    __shared__ int wsum[32];
    __shared__ int carry_s;
    int tid = threadIdx.x, lane = tid & 31, wi = tid >> 5;
    if (tid == 0) carry_s = 0;
    __syncthreads();
    for (int base = 0; base < N_NODES; base += 4096) {
        int i0 = base + tid * 4;
        int4 c = make_int4(0, 0, 0, 0);
        if (i0 + 3 < N_NODES) {
            c = *(const int4*)&g_cnt[i0];
        } else {
            if (i0 + 0 < N_NODES) c.x = g_cnt[i0 + 0];
            if (i0 + 1 < N_NODES) c.y = g_cnt[i0 + 1];
            if (i0 + 2 < N_NODES) c.z = g_cnt[i0 + 2];
            if (i0 + 3 < N_NODES) c.w = g_cnt[i0 + 3];
        }
        int tot = c.x + c.y + c.z + c.w;
        int incl = tot;
        #pragma unroll
        for (int d = 1; d < 32; d <<= 1) {
            int y = __shfl_up_sync(0xffffffffu, incl, d);
            if (lane >= d) incl += y;
        }
        if (lane == 31) wsum[wi] = incl;
        __syncthreads();
        if (wi == 0) {
            int s = wsum[lane];
            int inc2 = s;
            #pragma unroll
            for (int d = 1; d < 32; d <<= 1) {
                int y = __shfl_up_sync(0xffffffffu, inc2, d);
                if (lane >= d) inc2 += y;
            }
            wsum[lane] = inc2 - s;   // exclusive warp offsets
        }
        __syncthreads();
        int excl = carry_s + wsum[wi] + (incl - tot);
        int e0 = excl;
        int e1 = e0 + c.x;
        int e2 = e1 + c.y;
        int e3 = e2 + c.z;
        if (i0 + 0 < N_NODES) { g_row[i0 + 0] = e0; g_cur[i0 + 0] = e0; }
        if (i0 + 1 < N_NODES) { g_row[i0 + 1] = e1; g_cur[i0 + 1] = e1; }
        if (i0 + 2 < N_NODES) { g_row[i0 + 2] = e2; g_cur[i0 + 2] = e2; }
        if (i0 + 3 < N_NODES) { g_row[i0 + 3] = e3; g_cur[i0 + 3] = e3; }
        __syncthreads();
        if (tid == 1023) carry_s = excl + tot;
        __syncthreads();
    }
    if (threadIdx.x == 0) g_row[N_NODES] = carry_s;   // == N_EDGES
}

__global__ void build_kernel(const int* __restrict__ src, const int* __restrict__ tgt,
                             const float* __restrict__ sign, const float* __restrict__ syn_cnt,
                             const float* __restrict__ syn_str) {
    int e = blockIdx.x * blockDim.x + threadIdx.x;
    if (e < N_EDGES) {
        float w = sign[e] * fmaxf(syn_cnt[e], 0.f) * fmaxf(syn_str[e], 0.f);
        unsigned short hw = __half_as_ushort(__float2half(w));
        unsigned rec = (unsigned)src[e] | ((unsigned)hw << 16);
        int p = atomicAdd(&g_cur[tgt[e]], 1);
        g_edges[p] = rec;   // single 4B scatter
    }
}

__global__ void init_kernel(const float* __restrict__ bias, const float* __restrict__ tc) {
    int n = blockIdx.x * blockDim.x + threadIdx.x;
    if (n < N_NODES) {
        float tau = fmaxf(tc[n], DT);
        float a = DT / tau;
        float b = bias[n];
        g_ab[n] = make_float2(a, a * b);
        g_vstate[n] = make_float4(b, b, b, b);
        float r = fmaxf(b, 0.f);
        __half2 h = __floats2half2_rn(r, r);
        uint2 u; u.x = *(unsigned*)&h; u.y = u.x;
        g_rates[0][n] = u;
    }
    if (blockIdx.x == 0 && threadIdx.x == 0) {
        g_arrive = 0u;
        g_epoch = 0u;
    }
}

// ---------------- persistent simulation kernel: all 50 steps in one launch ----------------
// 592 CTAs (4/SM guaranteed by launch bounds), tiles of 32 nodes (8 lanes/node),
// software grid barrier between steps (fence includes L1 invalidate on sm_103a).
__global__ void __launch_bounds__(256, 4) sim_kernel(const float* __restrict__ x,
                                                     float* __restrict__ out) {
    const int tid = threadIdx.x;
    const int sub = tid & 7;
    const int oct = tid >> 3;        // node within tile, 0..31
    __shared__ float sh[128];        // [node_in_tile][batch]

    for (int t = 0; t < T_STEPS; t++) {
        const uint2* __restrict__ rin = g_rates[t & 1];
        __half* __restrict__ rout = (__half*)g_rates[(t & 1) ^ 1];

        for (int tile = blockIdx.x; tile < NT; tile += SIM_CTAS) {
            const int node0 = tile * 32;
            const int n = node0 + oct;
            int beg = 0, end = 0;
            if (n < N_NODES) { beg = g_row[n]; end = g_row[n + 1]; }

            float4 acc = make_float4(0.f, 0.f, 0.f, 0.f);
            int e = beg + sub;

            // main loop: 4 edges/lane/iter, 8 independent loads in flight
            while (e + 24 < end) {
                unsigned e0 = __ldg(&g_edges[e]);
                unsigned e1 = __ldg(&g_edges[e + 8]);
                unsigned e2 = __ldg(&g_edges[e + 16]);
                unsigned e3 = __ldg(&g_edges[e + 24]);
                uint2 r0 = __ldg(&rin[e0 & 0xFFFFu]);
                uint2 r1 = __ldg(&rin[e1 & 0xFFFFu]);
                uint2 r2 = __ldg(&rin[e2 & 0xFFFFu]);
                uint2 r3 = __ldg(&rin[e3 & 0xFFFFu]);
                float w0 = __half2float(__ushort_as_half((unsigned short)(e0 >> 16)));
                float w1 = __half2float(__ushort_as_half((unsigned short)(e1 >> 16)));
                float w2 = __half2float(__ushort_as_half((unsigned short)(e2 >> 16)));
                float w3 = __half2float(__ushort_as_half((unsigned short)(e3 >> 16)));
                float2 l0 = __half22float2(*(__half2*)&r0.x);
                float2 h0 = __half22float2(*(__half2*)&r0.y);
                float2 l1 = __half22float2(*(__half2*)&r1.x);
                float2 h1 = __half22float2(*(__half2*)&r1.y);
                float2 l2 = __half22float2(*(__half2*)&r2.x);
                float2 h2 = __half22float2(*(__half2*)&r2.y);
                float2 l3 = __half22float2(*(__half2*)&r3.x);
                float2 h3 = __half22float2(*(__half2*)&r3.y);
                acc.x += w0 * l0.x + w1 * l1.x + w2 * l2.x + w3 * l3.x;
                acc.y += w0 * l0.y + w1 * l1.y + w2 * l2.y + w3 * l3.y;
                acc.z += w0 * h0.x + w1 * h1.x + w2 * h2.x + w3 * h3.x;
                acc.w += w0 * h0.y + w1 * h1.y + w2 * h2.y + w3 * h3.y;
                e += 32;
            }
            while (e < end) {
                unsigned e0 = __ldg(&g_edges[e]);
                uint2 r0 = __ldg(&rin[e0 & 0xFFFFu]);
                float w0 = __half2float(__ushort_as_half((unsigned short)(e0 >> 16)));
                float2 l0 = __half22float2(*(__half2*)&r0.x);
                float2 h0 = __half22float2(*(__half2*)&r0.y);
                acc.x += w0 * l0.x;
                acc.y += w0 * l0.y;
                acc.z += w0 * h0.x;
                acc.w += w0 * h0.y;
                e += 8;
            }

            // octet reduction (3 rounds within each 8-lane group)
            #pragma unroll
            for (int d = 4; d; d >>= 1) {
                acc.x += __shfl_xor_sync(0xffffffffu, acc.x, d);
                acc.y += __shfl_xor_sync(0xffffffffu, acc.y, d);
                acc.z += __shfl_xor_sync(0xffffffffu, acc.z, d);
                acc.w += __shfl_xor_sync(0xffffffffu, acc.w, d);
            }

            if (sub == 0) {
                sh[oct * 4 + 0] = acc.x;
                sh[oct * 4 + 1] = acc.y;
                sh[oct * 4 + 2] = acc.z;
                sh[oct * 4 + 3] = acc.w;
            }
            __syncthreads();

            // epilogue: 128 threads = 32 nodes x 4 batches, coalesced
            if (tid < 128) {
                int j = tid >> 2;
                int b = tid & 3;
                int nn = node0 + j;
                if (nn < N_NODES) {
                    float vold = ((const float*)g_vstate)[node0 * 4 + tid];
                    float s    = sh[tid];
                    float2 ab  = g_ab[nn];
                    int   xi   = (b * T_STEPS + t) * N_NODES + nn;
                    float xv   = __ldg(&x[xi]);
                    float vnew = vold + ab.x * (s + xv - vold) + ab.y;
                    ((float*)g_vstate)[node0 * 4 + tid] = vnew;
                    float r = fmaxf(vnew, 0.f);
                    out[xi] = r;
                    rout[node0 * 4 + tid] = __float2half(r);   // 256B contiguous per tile
                }
            }
            __syncthreads();   // protect sh reuse next tile
        }

        // grid barrier between steps (not after the last)
        if (t + 1 < T_STEPS) {
            if (tid == 0) {
                __threadfence();   // publish rout/out; emits CCTL.IVALL (L1 flush) on sm_103a
                unsigned a = atomicAdd(&g_arrive, 1u);
                if (a == (unsigned)SIM_CTAS * (unsigned)(t + 1) - 1u) {
                    g_epoch = (unsigned)(t + 1);           // release
                } else {
                    while (g_epoch < (unsigned)(t + 1)) __nanosleep(64);
                }
                __threadfence();   // acquire + invalidate L1 before next step's gathers
            }
            __syncthreads();
        }
    }
}

// ---------------- launch ----------------
extern "C" void kernel_launch(void* const* d_in, const int* in_sizes, int n_in,
                              void* d_out, int out_size) {
    const float* x            = (const float*)d_in[0];   // [B, T, N]
    const float* bias         = (const float*)d_in[1];   // [N]
    const float* time_const   = (const float*)d_in[2];   // [N]
    const float* sign         = (const float*)d_in[3];   // [E]
    const float* syn_count    = (const float*)d_in[4];   // [E]
    const float* syn_strength = (const float*)d_in[5];   // [E]
    const int*   src_idx      = (const int*)d_in[6];     // [E]
    const int*   tgt_idx      = (const int*)d_in[7];     // [E]
    float* out = (float*)d_out;                          // [B, T, N]

    const int TB = 256;
    zero_cnt_kernel<<<(N_NODES + TB - 1) / TB, TB>>>();
    hist_kernel<<<(N_EDGES + TB - 1) / TB, TB>>>(tgt_idx);
    scan_kernel<<<1, 1024>>>();
    build_kernel<<<(N_EDGES + TB - 1) / TB, TB>>>(src_idx, tgt_idx, sign, syn_count, syn_strength);
    init_kernel<<<(N_NODES + TB - 1) / TB, TB>>>(bias, time_const);

    sim_kernel<<<SIM_CTAS, 256>>>(x, out);
}

// round 7
// speedup vs baseline: 1.0899x; 1.0899x over previous
#include <cuda_runtime.h>
#include <cuda_fp16.h>

#define N_NODES 50000
#define N_EDGES 1600000
#define BATCH 4
#define T_STEPS 50
#define DT 0.02f

// ---------------- static device scratch (no allocations allowed) ----------------
__device__ __align__(16) int g_cnt[N_NODES];
__device__ int      g_row[N_NODES + 1];
__device__ int      g_cur[N_NODES];
__device__ unsigned g_edges[N_EDGES];      // lo16 = src node, hi16 = half(weight); target-sorted
__device__ float2   g_ab[N_NODES];         // {alpha, alpha*bias}
__device__ float4   g_vstate[N_NODES];     // fp32 state, node-major x 4 batches
__device__ uint2    g_rates[2][N_NODES];   // half4 relu(v), double-buffered

// ---------------- preprocessing ----------------

__global__ void zero_cnt_kernel() {
    int n = blockIdx.x * blockDim.x + threadIdx.x;
    if (n < N_NODES) g_cnt[n] = 0;
}

__global__ void hist_kernel(const int* __restrict__ tgt) {
    int e = blockIdx.x * blockDim.x + threadIdx.x;
    if (e < N_EDGES) atomicAdd(&g_cnt[tgt[e]], 1);
}

// Single-CTA exclusive scan of g_cnt -> g_row/g_cur. 1024 threads, 4 elems/thread.
__global__ void scan_kernel() {
    __shared__ int wsum[32];
    __shared__ int carry_s;
    int tid = threadIdx.x, lane = tid & 31, wi = tid >> 5;
    if (tid == 0) carry_s = 0;
    __syncthreads();
    for (int base = 0; base < N_NODES; base += 4096) {
        int i0 = base + tid * 4;
        int4 c = make_int4(0, 0, 0, 0);
        if (i0 + 3 < N_NODES) {
            c = *(const int4*)&g_cnt[i0];
        } else {
            if (i0 + 0 < N_NODES) c.x = g_cnt[i0 + 0];
            if (i0 + 1 < N_NODES) c.y = g_cnt[i0 + 1];
            if (i0 + 2 < N_NODES) c.z = g_cnt[i0 + 2];
            if (i0 + 3 < N_NODES) c.w = g_cnt[i0 + 3];
        }
        int tot = c.x + c.y + c.z + c.w;
        int incl = tot;
        #pragma unroll
        for (int d = 1; d < 32; d <<= 1) {
            int y = __shfl_up_sync(0xffffffffu, incl, d);
            if (lane >= d) incl += y;
        }
        if (lane == 31) wsum[wi] = incl;
        __syncthreads();
        if (wi == 0) {
            int s = wsum[lane];
            int inc2 = s;
            #pragma unroll
            for (int d = 1; d < 32; d <<= 1) {
                int y = __shfl_up_sync(0xffffffffu, inc2, d);
                if (lane >= d) inc2 += y;
            }
            wsum[lane] = inc2 - s;   // exclusive warp offsets
        }
        __syncthreads();
        int excl = carry_s + wsum[wi] + (incl - tot);
        int e0 = excl;
        int e1 = e0 + c.x;
        int e2 = e1 + c.y;
        int e3 = e2 + c.z;
        if (i0 + 0 < N_NODES) { g_row[i0 + 0] = e0; g_cur[i0 + 0] = e0; }
        if (i0 + 1 < N_NODES) { g_row[i0 + 1] = e1; g_cur[i0 + 1] = e1; }
        if (i0 + 2 < N_NODES) { g_row[i0 + 2] = e2; g_cur[i0 + 2] = e2; }
        if (i0 + 3 < N_NODES) { g_row[i0 + 3] = e3; g_cur[i0 + 3] = e3; }
        __syncthreads();
        if (tid == 1023) carry_s = excl + tot;
        __syncthreads();
    }
    if (threadIdx.x == 0) g_row[N_NODES] = carry_s;   // == N_EDGES
}

__global__ void build_kernel(const int* __restrict__ src, const int* __restrict__ tgt,
                             const float* __restrict__ sign, const float* __restrict__ syn_cnt,
                             const float* __restrict__ syn_str) {
    int e = blockIdx.x * blockDim.x + threadIdx.x;
    if (e < N_EDGES) {
        float w = sign[e] * fmaxf(syn_cnt[e], 0.f) * fmaxf(syn_str[e], 0.f);
        unsigned short hw = __half_as_ushort(__float2half(w));
        unsigned rec = (unsigned)src[e] | ((unsigned)hw << 16);
        int p = atomicAdd(&g_cur[tgt[e]], 1);
        g_edges[p] = rec;   // single 4B scatter
    }
}

__global__ void init_kernel(const float* __restrict__ bias, const float* __restrict__ tc) {
    int n = blockIdx.x * blockDim.x + threadIdx.x;
    if (n < N_NODES) {
        float tau = fmaxf(tc[n], DT);
        float a = DT / tau;
        float b = bias[n];
        g_ab[n] = make_float2(a, a * b);
        g_vstate[n] = make_float4(b, b, b, b);
        float r = fmaxf(b, 0.f);
        __half2 h = __floats2half2_rn(r, r);
        uint2 u; u.x = *(unsigned*)&h; u.y = u.x;
        g_rates[0][n] = u;
    }
}

// ---------------- per-step kernel: single wave ----------------
// CTA = 256 threads = 64 nodes (4 lanes/node). Grid = 782 CTAs -> 200k threads,
// fits in one wave (capacity ~303k threads). 4x-unrolled gather loop for MLP.
__global__ void __launch_bounds__(256, 6) step_kernel(const float* __restrict__ x,
                                                      float* __restrict__ out,
                                                      int t, int parity) {
    const int node0 = blockIdx.x * 64;
    const int tid = threadIdx.x;
    const int sub = tid & 3;
    const int quad = tid >> 2;       // node within CTA, 0..63
    const int n = node0 + quad;

    const uint2* __restrict__ rin = g_rates[parity];
    __half* __restrict__ rout = (__half*)g_rates[parity ^ 1];

    int beg = 0, end = 0;
    if (n < N_NODES) { beg = g_row[n]; end = g_row[n + 1]; }

    float4 acc = make_float4(0.f, 0.f, 0.f, 0.f);
    int e = beg + sub;

    // main loop: 4 edges per lane per iteration, 8 independent loads in flight
    while (e + 12 < end) {
        unsigned e0 = __ldg(&g_edges[e]);
        unsigned e1 = __ldg(&g_edges[e + 4]);
        unsigned e2 = __ldg(&g_edges[e + 8]);
        unsigned e3 = __ldg(&g_edges[e + 12]);
        uint2 r0 = __ldg(&rin[e0 & 0xFFFFu]);
        uint2 r1 = __ldg(&rin[e1 & 0xFFFFu]);
        uint2 r2 = __ldg(&rin[e2 & 0xFFFFu]);
        uint2 r3 = __ldg(&rin[e3 & 0xFFFFu]);
        float w0 = __half2float(__ushort_as_half((unsigned short)(e0 >> 16)));
        float w1 = __half2float(__ushort_as_half((unsigned short)(e1 >> 16)));
        float w2 = __half2float(__ushort_as_half((unsigned short)(e2 >> 16)));
        float w3 = __half2float(__ushort_as_half((unsigned short)(e3 >> 16)));
        float2 l0 = __half22float2(*(__half2*)&r0.x);
        float2 h0 = __half22float2(*(__half2*)&r0.y);
        float2 l1 = __half22float2(*(__half2*)&r1.x);
        float2 h1 = __half22float2(*(__half2*)&r1.y);
        float2 l2 = __half22float2(*(__half2*)&r2.x);
        float2 h2 = __half22float2(*(__half2*)&r2.y);
        float2 l3 = __half22float2(*(__half2*)&r3.x);
        float2 h3 = __half22float2(*(__half2*)&r3.y);
        acc.x += w0 * l0.x + w1 * l1.x + w2 * l2.x + w3 * l3.x;
        acc.y += w0 * l0.y + w1 * l1.y + w2 * l2.y + w3 * l3.y;
        acc.z += w0 * h0.x + w1 * h1.x + w2 * h2.x + w3 * h3.x;
        acc.w += w0 * h0.y + w1 * h1.y + w2 * h2.y + w3 * h3.y;
        e += 16;
    }
    while (e < end) {
        unsigned e0 = __ldg(&g_edges[e]);
        uint2 r0 = __ldg(&rin[e0 & 0xFFFFu]);
        float w0 = __half2float(__ushort_as_half((unsigned short)(e0 >> 16)));
        float2 l0 = __half22float2(*(__half2*)&r0.x);
        float2 h0 = __half22float2(*(__half2*)&r0.y);
        acc.x += w0 * l0.x;
        acc.y += w0 * l0.y;
        acc.z += w0 * h0.x;
        acc.w += w0 * h0.y;
        e += 4;
    }

    // quad reduction (2 rounds within each 4-lane group)
    #pragma unroll
    for (int d = 2; d; d >>= 1) {
        acc.x += __shfl_xor_sync(0xffffffffu, acc.x, d);
        acc.y += __shfl_xor_sync(0xffffffffu, acc.y, d);
        acc.z += __shfl_xor_sync(0xffffffffu, acc.z, d);
        acc.w += __shfl_xor_sync(0xffffffffu, acc.w, d);
    }

    __shared__ float sh[256];   // [node_in_cta][batch]
    if (sub == 0) {
        sh[quad * 4 + 0] = acc.x;
        sh[quad * 4 + 1] = acc.y;
        sh[quad * 4 + 2] = acc.z;
        sh[quad * 4 + 3] = acc.w;
    }
    __syncthreads();

    // epilogue: all 256 threads = 64 nodes x 4 batches, fully coalesced v/rates
    {
        int j = tid >> 2;
        int b = tid & 3;
        int nn = node0 + j;
        if (nn < N_NODES) {
            float vold = ((const float*)g_vstate)[node0 * 4 + tid];
            float s    = sh[tid];
            float2 ab  = g_ab[nn];
            int   xi   = (b * T_STEPS + t) * N_NODES + nn;
            float xv   = __ldg(&x[xi]);
            float vnew = vold + ab.x * (s + xv - vold) + ab.y;
            ((float*)g_vstate)[node0 * 4 + tid] = vnew;
            float r = fmaxf(vnew, 0.f);
            out[xi] = r;
            rout[node0 * 4 + tid] = __float2half(r);   // 512B contiguous per CTA
        }
    }
}

// ---------------- launch ----------------
extern "C" void kernel_launch(void* const* d_in, const int* in_sizes, int n_in,
                              void* d_out, int out_size) {
    const float* x            = (const float*)d_in[0];   // [B, T, N]
    const float* bias         = (const float*)d_in[1];   // [N]
    const float* time_const   = (const float*)d_in[2];   // [N]
    const float* sign         = (const float*)d_in[3];   // [E]
    const float* syn_count    = (const float*)d_in[4];   // [E]
    const float* syn_strength = (const float*)d_in[5];   // [E]
    const int*   src_idx      = (const int*)d_in[6];     // [E]
    const int*   tgt_idx      = (const int*)d_in[7];     // [E]
    float* out = (float*)d_out;                          // [B, T, N]

    const int TB = 256;
    zero_cnt_kernel<<<(N_NODES + TB - 1) / TB, TB>>>();
    hist_kernel<<<(N_EDGES + TB - 1) / TB, TB>>>(tgt_idx);
    scan_kernel<<<1, 1024>>>();
    build_kernel<<<(N_EDGES + TB - 1) / TB, TB>>>(src_idx, tgt_idx, sign, syn_count, syn_strength);
    init_kernel<<<(N_NODES + TB - 1) / TB, TB>>>(bias, time_const);

    const int STEP_GRID = (N_NODES + 63) / 64;   // 782
    for (int t = 0; t < T_STEPS; t++) {
        step_kernel<<<STEP_GRID, 256>>>(x, out, t, t & 1);
    }
}

// round 10
// speedup vs baseline: 1.1023x; 1.0114x over previous
#include <cuda_runtime.h>
#include <cuda_fp16.h>

#define N_NODES 50000
#define N_EDGES 1600000
#define E_PAD_MAX 2400000     // 1.6M + 50000*15 = 2.35M worst case, rounded up
#define BATCH 4
#define T_STEPS 50
#define DT 0.02f

// ---------------- static device scratch (no allocations allowed) ----------------
__device__ __align__(16) int g_cnt[N_NODES];
__device__ int      g_row[N_NODES + 1];
__device__ int      g_cur[N_NODES];
__device__ __align__(16) unsigned g_src32[E_PAD_MAX];  // src index (pad: 0)
__device__ __align__(16) unsigned g_wh2[E_PAD_MAX];    // half2{w,w}  (pad: 0)
__device__ float2   g_ab[N_NODES];         // {alpha, alpha*bias}
__device__ float4   g_vstate[N_NODES];     // fp32 state, node-major x 4 batches
__device__ uint2    g_rates[2][N_NODES];   // half4 relu(v), double-buffered

// ---------------- preprocessing ----------------

__global__ void zero_cnt_kernel() {
    int n = blockIdx.x * blockDim.x + threadIdx.x;
    if (n < N_NODES) g_cnt[n] = 0;
}

__global__ void fill_pad_kernel() {
    int i = blockIdx.x * blockDim.x + threadIdx.x;
    if (i < E_PAD_MAX) { g_src32[i] = 0u; g_wh2[i] = 0u; }
}

__global__ void hist_kernel(const int* __restrict__ tgt) {
    int e = blockIdx.x * blockDim.x + threadIdx.x;
    if (e < N_EDGES) atomicAdd(&g_cnt[tgt[e]], 1);
}

// Single-CTA exclusive scan of PADDED counts -> g_row/g_cur. 1024 threads, 4/thread.
__global__ void scan_kernel() {
    __shared__ int wsum[32];
    __shared__ int carry_s;
    int tid = threadIdx.x, lane = tid & 31, wi = tid >> 5;
    if (tid == 0) carry_s = 0;
    __syncthreads();
    for (int base = 0; base < N_NODES; base += 4096) {
        int i0 = base + tid * 4;
        int4 c = make_int4(0, 0, 0, 0);
        if (i0 + 3 < N_NODES) {
            c = *(const int4*)&g_cnt[i0];
        } else {
            if (i0 + 0 < N_NODES) c.x = g_cnt[i0 + 0];
            if (i0 + 1 < N_NODES) c.y = g_cnt[i0 + 1];
            if (i0 + 2 < N_NODES) c.z = g_cnt[i0 + 2];
            if (i0 + 3 < N_NODES) c.w = g_cnt[i0 + 3];
        }
        // pad each row's count to a multiple of 16 edges
        c.x = (c.x + 15) & ~15;
        c.y = (c.y + 15) & ~15;
        c.z = (c.z + 15) & ~15;
        c.w = (c.w + 15) & ~15;
        int tot = c.x + c.y + c.z + c.w;
        int incl = tot;
        #pragma unroll
        for (int d = 1; d < 32; d <<= 1) {
            int y = __shfl_up_sync(0xffffffffu, incl, d);
            if (lane >= d) incl += y;
        }
        if (lane == 31) wsum[wi] = incl;
        __syncthreads();
        if (wi == 0) {
            int s = wsum[lane];
            int inc2 = s;
            #pragma unroll
            for (int d = 1; d < 32; d <<= 1) {
                int y = __shfl_up_sync(0xffffffffu, inc2, d);
                if (lane >= d) inc2 += y;
            }
            wsum[lane] = inc2 - s;   // exclusive warp offsets
        }
        __syncthreads();
        int excl = carry_s + wsum[wi] + (incl - tot);
        int e0 = excl;
        int e1 = e0 + c.x;
        int e2 = e1 + c.y;
        int e3 = e2 + c.z;
        if (i0 + 0 < N_NODES) { g_row[i0 + 0] = e0; g_cur[i0 + 0] = e0; }
        if (i0 + 1 < N_NODES) { g_row[i0 + 1] = e1; g_cur[i0 + 1] = e1; }
        if (i0 + 2 < N_NODES) { g_row[i0 + 2] = e2; g_cur[i0 + 2] = e2; }
        if (i0 + 3 < N_NODES) { g_row[i0 + 3] = e3; g_cur[i0 + 3] = e3; }
        __syncthreads();
        if (tid == 1023) carry_s = excl + tot;
        __syncthreads();
    }
    if (threadIdx.x == 0) g_row[N_NODES] = carry_s;   // padded total <= E_PAD_MAX
}

__global__ void build_kernel(const int* __restrict__ src, const int* __restrict__ tgt,
                             const float* __restrict__ sign, const float* __restrict__ syn_cnt,
                             const float* __restrict__ syn_str) {
    int e = blockIdx.x * blockDim.x + threadIdx.x;
    if (e < N_EDGES) {
        float w = sign[e] * fmaxf(syn_cnt[e], 0.f) * fmaxf(syn_str[e], 0.f);
        __half hw = __float2half_rn(w);
        __half2 h2 = __half2half2(hw);
        int p = atomicAdd(&g_cur[tgt[e]], 1);
        g_src32[p] = (unsigned)src[e];
        g_wh2[p] = *(unsigned*)&h2;
    }
}

__global__ void init_kernel(const float* __restrict__ bias, const float* __restrict__ tc) {
    int n = blockIdx.x * blockDim.x + threadIdx.x;
    if (n < N_NODES) {
        float tau = fmaxf(tc[n], DT);
        float a = DT / tau;
        float b = bias[n];
        g_ab[n] = make_float2(a, a * b);
        g_vstate[n] = make_float4(b, b, b, b);
        float r = fmaxf(b, 0.f);
        __half2 h = __floats2half2_rn(r, r);
        uint2 u; u.x = *(unsigned*)&h; u.y = u.x;
        g_rates[0][n] = u;
    }
}

// one 4-edge chunk: 2x LDG.128 + 4x LDG.64 + 8 HFMA2, accumulates into half2 pair
__device__ __forceinline__ void chunk4(const uint2* __restrict__ rin, int e,
                                       __half2& a01, __half2& a23) {
    uint4 s4 = __ldg((const uint4*)&g_src32[e]);
    uint4 w4 = __ldg((const uint4*)&g_wh2[e]);
    uint2 r0 = __ldg(&rin[s4.x]);
    uint2 r1 = __ldg(&rin[s4.y]);
    uint2 r2 = __ldg(&rin[s4.z]);
    uint2 r3 = __ldg(&rin[s4.w]);
    a01 = __hfma2(*(__half2*)&w4.x, *(__half2*)&r0.x, a01);
    a23 = __hfma2(*(__half2*)&w4.x, *(__half2*)&r0.y, a23);
    a01 = __hfma2(*(__half2*)&w4.y, *(__half2*)&r1.x, a01);
    a23 = __hfma2(*(__half2*)&w4.y, *(__half2*)&r1.y, a23);
    a01 = __hfma2(*(__half2*)&w4.z, *(__half2*)&r2.x, a01);
    a23 = __hfma2(*(__half2*)&w4.z, *(__half2*)&r2.y, a23);
    a01 = __hfma2(*(__half2*)&w4.w, *(__half2*)&r3.x, a01);
    a23 = __hfma2(*(__half2*)&w4.w, *(__half2*)&r3.y, a23);
}

// ---------------- per-step kernel ----------------
// CTA = 256 threads = 64 nodes (4 lanes/node). Grid = 782 -> single wave.
// Rows padded to multiples of 16 edges: every quad iteration is a full 16-edge
// chunk, no remainder. fp16 HFMA2 accumulation, flushed to fp32 every 8 edges.
__global__ void __launch_bounds__(256, 6) step_kernel(const float* __restrict__ x,
                                                      float* __restrict__ out,
                                                      int t, int parity) {
    const int node0 = blockIdx.x * 64;
    const int tid = threadIdx.x;
    const int sub = tid & 3;
    const int quad = tid >> 2;       // node within CTA, 0..63
    const int n = node0 + quad;

    const uint2* __restrict__ rin = g_rates[parity];
    __half* __restrict__ rout = (__half*)g_rates[parity ^ 1];

    int beg = 0, end = 0;
    if (n < N_NODES) { beg = g_row[n]; end = g_row[n + 1]; }

    float2 f01 = make_float2(0.f, 0.f);
    float2 f23 = make_float2(0.f, 0.f);
    const __half2 hz = __float2half2_rn(0.f);

    int e = beg + (sub << 2);
    // pair loop: 2 chunks (8 edges/lane) per flush
    while (e + 16 < end) {
        __half2 a01 = hz, a23 = hz;
        chunk4(rin, e, a01, a23);
        chunk4(rin, e + 16, a01, a23);
        float2 p01 = __half22float2(a01);
        float2 p23 = __half22float2(a23);
        f01.x += p01.x; f01.y += p01.y;
        f23.x += p23.x; f23.y += p23.y;
        e += 32;
    }
    if (e < end) {
        __half2 a01 = hz, a23 = hz;
        chunk4(rin, e, a01, a23);
        float2 p01 = __half22float2(a01);
        float2 p23 = __half22float2(a23);
        f01.x += p01.x; f01.y += p01.y;
        f23.x += p23.x; f23.y += p23.y;
    }

    // quad reduction (2 rounds within each 4-lane group)
    #pragma unroll
    for (int d = 2; d; d >>= 1) {
        f01.x += __shfl_xor_sync(0xffffffffu, f01.x, d);
        f01.y += __shfl_xor_sync(0xffffffffu, f01.y, d);
        f23.x += __shfl_xor_sync(0xffffffffu, f23.x, d);
        f23.y += __shfl_xor_sync(0xffffffffu, f23.y, d);
    }

    __shared__ float sh[256];   // [node_in_cta][batch]
    if (sub == 0) {
        sh[quad * 4 + 0] = f01.x;
        sh[quad * 4 + 1] = f01.y;
        sh[quad * 4 + 2] = f23.x;
        sh[quad * 4 + 3] = f23.y;
    }
    __syncthreads();

    // epilogue: all 256 threads = 64 nodes x 4 batches, fully coalesced v/rates
    {
        int j = tid >> 2;
        int b = tid & 3;
        int nn = node0 + j;
        if (nn < N_NODES) {
            float vold = ((const float*)g_vstate)[node0 * 4 + tid];
            float s    = sh[tid];
            float2 ab  = g_ab[nn];
            int   xi   = (b * T_STEPS + t) * N_NODES + nn;
            float xv   = __ldg(&x[xi]);
            float vnew = vold + ab.x * (s + xv - vold) + ab.y;
            ((float*)g_vstate)[node0 * 4 + tid] = vnew;
            float r = fmaxf(vnew, 0.f);
            out[xi] = r;
            rout[node0 * 4 + tid] = __float2half(r);   // 512B contiguous per CTA
        }
    }
}

// ---------------- launch ----------------
extern "C" void kernel_launch(void* const* d_in, const int* in_sizes, int n_in,
                              void* d_out, int out_size) {
    const float* x            = (const float*)d_in[0];   // [B, T, N]
    const float* bias         = (const float*)d_in[1];   // [N]
    const float* time_const   = (const float*)d_in[2];   // [N]
    const float* sign         = (const float*)d_in[3];   // [E]
    const float* syn_count    = (const float*)d_in[4];   // [E]
    const float* syn_strength = (const float*)d_in[5];   // [E]
    const int*   src_idx      = (const int*)d_in[6];     // [E]
    const int*   tgt_idx      = (const int*)d_in[7];     // [E]
    float* out = (float*)d_out;                          // [B, T, N]

    const int TB = 256;
    zero_cnt_kernel<<<(N_NODES + TB - 1) / TB, TB>>>();
    fill_pad_kernel<<<(E_PAD_MAX + TB - 1) / TB, TB>>>();
    hist_kernel<<<(N_EDGES + TB - 1) / TB, TB>>>(tgt_idx);
    scan_kernel<<<1, 1024>>>();
    build_kernel<<<(N_EDGES + TB - 1) / TB, TB>>>(src_idx, tgt_idx, sign, syn_count, syn_strength);
    init_kernel<<<(N_NODES + TB - 1) / TB, TB>>>(bias, time_const);

    const int STEP_GRID = (N_NODES + 63) / 64;   // 782
    for (int t = 0; t < T_STEPS; t++) {
        step_kernel<<<STEP_GRID, 256>>>(x, out, t, t & 1);
    }
}